// round 15
// baseline (speedup 1.0000x reference)
#include <cuda_runtime.h>
#include <stdint.h>
#include <math.h>

#define N_ENTC 100000
#define N_ROWI 30000
#define NTOT   130000
#define M2     (2 * NTOT)
#define N_EDGE 200000
#define N_RELC 200

typedef unsigned long long u64;

// packed f32x2 FMA: two independent IEEE fp32 FMAs per instruction (Blackwell)
__device__ __forceinline__ u64 fma2(u64 a, u64 b, u64 c) {
    u64 d;
    asm("fma.rn.f32x2 %0, %1, %2, %3;" : "=l"(d) : "l"(a), "l"(b), "l"(c));
    return d;
}
__device__ __forceinline__ u64 bcast2(float v) {
    u64 r;
    asm("mov.b64 %0, {%1, %1};" : "=l"(r) : "f"(v));
    return r;
}
__device__ __forceinline__ void unpack2(u64 v, float& lo, float& hi) {
    asm("mov.b64 {%0, %1}, %2;" : "=f"(lo), "=f"(hi) : "l"(v));
}

// ---------------- scratch (static device globals; no allocation) ----------------
__device__ float g_inst[(size_t)N_ROWI * 256];
__device__ float g_xview[(size_t)NTOT * 256]; // exact fp32 x_all @ W_in + b_in  (FROZEN numerics)
__device__ float g_h[(size_t)NTOT * 256];     // exact fp32 x_view @ W_conv + b_conv
__device__ float g_xs[NTOT * 2];
__device__ float g_a1[N_EDGE * 2];
__device__ float g_a2[N_EDGE * 2];
__device__ float g_Dn[N_ENTC * 2];
__device__ float g_outagg[(size_t)N_ENTC * 256];
__device__ float g_es[(N_RELC + 1) * 2];
__device__ double g_colsum[256];
__device__ double g_colsq[256];
__device__ float g_scale[256];
__device__ float g_shift[256];

// ---------------- direct es, EXACT fp32 ----------------
__global__ void k_es(const float* __restrict__ rel_embed, const float* __restrict__ loop_rel,
                     const float* __restrict__ W_edge, const float* __restrict__ b_edge,
                     const float* __restrict__ W_sheaf) {
    __shared__ float row[256], ev[256];
    int t = threadIdx.x;
    int r = blockIdx.x;
    const float* src = (r < N_RELC) ? rel_embed + (size_t)r * 256 : loop_rel;
    row[t] = src[t];
    __syncthreads();
    float s = 0.f;
    for (int f = 0; f < 256; f++) s = fmaf(row[f], W_edge[(size_t)f * 256 + t], s);
    ev[t] = s + b_edge[t];
    __syncthreads();
    if (t < 2) {
        float acc = 0.f;
        for (int c = 0; c < 128; c++) {
            float em = 0.5f * (ev[c] + ev[c + 128]);
            acc = fmaf(em, W_sheaf[(size_t)(128 + c) * 2 + t], acc);
        }
        g_es[r * 2 + t] = acc;
    }
}

// r_out = rel_embed @ w_rel
__global__ void k_rout(const float* __restrict__ rel_embed, const float* __restrict__ w_rel,
                       float* __restrict__ out) {
    int r = blockIdx.x, c = threadIdx.x;
    __shared__ float row[256];
    row[c] = rel_embed[(size_t)r * 256 + c];
    __syncthreads();
    float s = 0.f;
    for (int f = 0; f < 256; f++) s = fmaf(row[f], w_rel[(size_t)f * 256 + c], s);
    out[(size_t)r * 256 + c] = s;
}

// instance-dict embedding
__global__ void k_inst(const float* __restrict__ x, const int* __restrict__ ids) {
    int r = blockIdx.x, c = threadIdx.x;
    float s = 0.f;
    int cnt = 0;
#pragma unroll
    for (int k = 0; k < 8; k++) {
        int id = ids[r * 8 + k];
        if (id >= 0) { s += x[(size_t)id * 256 + c]; cnt++; }
    }
    g_inst[(size_t)r * 256 + c] = s / (float)cnt;
}

// ---------------- GEMM1 (exact fp32 chains, f32x2 packed, double-buffered) ----------------
__global__ void k_gemm1(const float* __restrict__ x, const float* __restrict__ W_in,
                        const float* __restrict__ b_in) {
    __shared__ float As[2][8][128];
    __shared__ float Bs[2][8][128];
    int tid = threadIdx.x;
    int tx = tid & 15, ty = tid >> 4;
    int rowBase = blockIdx.x * 128;
    int colBase = blockIdx.y * 128;
    u64 acc2[8][4] = {};
    int arow = tid >> 1, acol = (tid & 1) * 4;
    int brow = tid >> 5, bcol = (tid & 31) * 4;
    int gr_a = rowBase + arow;
    bool a_ok = (gr_a < NTOT);
    const float* srcA = a_ok
        ? ((gr_a < N_ENTC) ? x + (size_t)gr_a * 256 : g_inst + (size_t)(gr_a - N_ENTC) * 256)
        : x;

    {
        float4 av = make_float4(0.f, 0.f, 0.f, 0.f);
        if (a_ok) av = *(const float4*)(srcA + acol);
        As[0][acol + 0][arow] = av.x;
        As[0][acol + 1][arow] = av.y;
        As[0][acol + 2][arow] = av.z;
        As[0][acol + 3][arow] = av.w;
        *(float4*)(&Bs[0][brow][bcol]) =
            *(const float4*)(W_in + (size_t)brow * 256 + colBase + bcol);
    }
    __syncthreads();
    int buf = 0;
    for (int k0 = 0; k0 < 256; k0 += 8) {
        float4 av2 = make_float4(0.f, 0.f, 0.f, 0.f), bv2;
        bool nxt = (k0 + 8) < 256;
        if (nxt) {
            if (a_ok) av2 = *(const float4*)(srcA + k0 + 8 + acol);
            bv2 = *(const float4*)(W_in + (size_t)(k0 + 8 + brow) * 256 + colBase + bcol);
        }
#pragma unroll
        for (int kk = 0; kk < 8; kk++) {
            float a[8];
            *(float4*)(a)     = *(const float4*)(&As[buf][kk][ty * 8]);
            *(float4*)(a + 4) = *(const float4*)(&As[buf][kk][ty * 8 + 4]);
            ulonglong2 bq0 = *(const ulonglong2*)(&Bs[buf][kk][tx * 8]);
            ulonglong2 bq1 = *(const ulonglong2*)(&Bs[buf][kk][tx * 8 + 4]);
            u64 bp[4] = { bq0.x, bq0.y, bq1.x, bq1.y };
#pragma unroll
            for (int i = 0; i < 8; i++) {
                u64 pa = bcast2(a[i]);
#pragma unroll
                for (int jp = 0; jp < 4; jp++) acc2[i][jp] = fma2(pa, bp[jp], acc2[i][jp]);
            }
        }
        if (nxt) {
            int nb = buf ^ 1;
            As[nb][acol + 0][arow] = av2.x;
            As[nb][acol + 1][arow] = av2.y;
            As[nb][acol + 2][arow] = av2.z;
            As[nb][acol + 3][arow] = av2.w;
            *(float4*)(&Bs[nb][brow][bcol]) = bv2;
        }
        __syncthreads();
        buf ^= 1;
    }
#pragma unroll
    for (int i = 0; i < 8; i++) {
        int gr = rowBase + ty * 8 + i;
        if (gr < NTOT) {
            float o[8];
#pragma unroll
            for (int jp = 0; jp < 4; jp++) unpack2(acc2[i][jp], o[jp * 2], o[jp * 2 + 1]);
#pragma unroll
            for (int j = 0; j < 8; j += 4) {
                int col = colBase + tx * 8 + j;
                float4 v;
                v.x = o[j + 0] + b_in[col + 0];
                v.y = o[j + 1] + b_in[col + 1];
                v.z = o[j + 2] + b_in[col + 2];
                v.w = o[j + 3] + b_in[col + 3];
                *(float4*)(g_xview + (size_t)gr * 256 + col) = v;
            }
        }
    }
}

// ---------------- GEMM2 (exact fp32 chains, f32x2 packed, double-buffered) ----------------
__global__ void k_gemm2(const float* __restrict__ W_conv, const float* __restrict__ b_conv) {
    __shared__ float As[2][8][128];
    __shared__ float Bs[2][8][128];
    int tid = threadIdx.x;
    int tx = tid & 15, ty = tid >> 4;
    int rowBase = blockIdx.x * 128;
    u64 acc2[8][4] = {};
    int arow = tid >> 1, acol = (tid & 1) * 4;
    int brow = tid >> 5, bcol = (tid & 31) * 4;
    int gr_a = rowBase + arow;
    bool a_ok = (gr_a < M2);
    const float* srcA = g_xview + (size_t)gr_a * 128;

    {
        float4 av = make_float4(0.f, 0.f, 0.f, 0.f);
        if (a_ok) av = *(const float4*)(srcA + acol);
        As[0][acol + 0][arow] = av.x;
        As[0][acol + 1][arow] = av.y;
        As[0][acol + 2][arow] = av.z;
        As[0][acol + 3][arow] = av.w;
        *(float4*)(&Bs[0][brow][bcol]) =
            *(const float4*)(W_conv + (size_t)brow * 128 + bcol);
    }
    __syncthreads();
    int buf = 0;
    for (int k0 = 0; k0 < 128; k0 += 8) {
        float4 av2 = make_float4(0.f, 0.f, 0.f, 0.f), bv2;
        bool nxt = (k0 + 8) < 128;
        if (nxt) {
            if (a_ok) av2 = *(const float4*)(srcA + k0 + 8 + acol);
            bv2 = *(const float4*)(W_conv + (size_t)(k0 + 8 + brow) * 128 + bcol);
        }
#pragma unroll
        for (int kk = 0; kk < 8; kk++) {
            float a[8];
            *(float4*)(a)     = *(const float4*)(&As[buf][kk][ty * 8]);
            *(float4*)(a + 4) = *(const float4*)(&As[buf][kk][ty * 8 + 4]);
            ulonglong2 bq0 = *(const ulonglong2*)(&Bs[buf][kk][tx * 8]);
            ulonglong2 bq1 = *(const ulonglong2*)(&Bs[buf][kk][tx * 8 + 4]);
            u64 bp[4] = { bq0.x, bq0.y, bq1.x, bq1.y };
#pragma unroll
            for (int i = 0; i < 8; i++) {
                u64 pa = bcast2(a[i]);
#pragma unroll
                for (int jp = 0; jp < 4; jp++) acc2[i][jp] = fma2(pa, bp[jp], acc2[i][jp]);
            }
        }
        if (nxt) {
            int nb = buf ^ 1;
            As[nb][acol + 0][arow] = av2.x;
            As[nb][acol + 1][arow] = av2.y;
            As[nb][acol + 2][arow] = av2.z;
            As[nb][acol + 3][arow] = av2.w;
            *(float4*)(&Bs[nb][brow][bcol]) = bv2;
        }
        __syncthreads();
        buf ^= 1;
    }
#pragma unroll
    for (int i = 0; i < 8; i++) {
        int gr = rowBase + ty * 8 + i;
        if (gr < M2) {
            float o[8];
#pragma unroll
            for (int jp = 0; jp < 4; jp++) unpack2(acc2[i][jp], o[jp * 2], o[jp * 2 + 1]);
#pragma unroll
            for (int j = 0; j < 8; j += 4) {
                int col = tx * 8 + j;
                float4 v;
                v.x = o[j + 0] + b_conv[col + 0];
                v.y = o[j + 1] + b_conv[col + 1];
                v.z = o[j + 2] + b_conv[col + 2];
                v.w = o[j + 3] + b_conv[col + 3];
                *(float4*)(g_h + (size_t)gr * 128 + col) = v;
            }
        }
    }
}

// ---------------- direct xs, EXACT fp32 chain (FROZEN), smem-staged rows ----------------
#define XS_NODES 32
#define XS_STRIDE 258
__global__ void k_xs(const float* __restrict__ W_sheaf) {
    __shared__ float sx[XS_NODES * XS_STRIDE];
    int t = threadIdx.x;              // 0..63
    int rowBase = blockIdx.x * XS_NODES;
    int nvalid = NTOT - rowBase; if (nvalid > XS_NODES) nvalid = XS_NODES;
    const float2* src = (const float2*)(g_xview + (size_t)rowBase * 256);
    float2* dst = (float2*)sx;
    int total = nvalid * 128;
    for (int i = t; i < total; i += 64) {
        int row = i >> 7, q = i & 127;
        dst[row * 129 + q] = src[i];
    }
    __syncthreads();
    int nl = t >> 1, hd = t & 1;
    if (nl < nvalid) {
        const float* xv = sx + nl * XS_STRIDE;
        float z = 0.f;
        for (int c = 0; c < 128; c++) {
            float m = 0.5f * (xv[c] + xv[c + 128]);
            z = fmaf(m, W_sheaf[c * 2 + hd], z);
        }
        g_xs[(size_t)(rowBase + nl) * 2 + hd] = z;
    }
}

// alpha + Dn (entity slots only)
__global__ void k_alpha(const int* __restrict__ ei, const int* __restrict__ etype,
                        const float* __restrict__ b_sheaf) {
    int e = blockIdx.x * 256 + threadIdx.x;
    if (e >= N_EDGE) return;
    int nb = ei[e];
    int na = ei[N_EDGE + e] + N_ENTC;
    int r = etype[e];
#pragma unroll
    for (int hd = 0; hd < 2; hd++) {
        float base = g_es[r * 2 + hd] + b_sheaf[hd];
        float v1 = tanhf(g_xs[na * 2 + hd] + base);
        float v2 = tanhf(g_xs[nb * 2 + hd] + base);
        g_a1[e * 2 + hd] = v1;
        g_a2[e * 2 + hd] = v2;
        atomicAdd(&g_Dn[nb * 2 + hd], v2 * v2);
    }
}

// main scatter
__global__ void k_agg(const int* __restrict__ ei) {
    int warp = (blockIdx.x * blockDim.x + threadIdx.x) >> 5;
    int lane = threadIdx.x & 31;
    if (warp >= N_EDGE) return;
    int e = warp;
    int nb = ei[e];
    int na = ei[N_EDGE + e] + N_ENTC;
    const float4* ha = (const float4*)(g_h + (size_t)na * 256);
    const float4* hb = (const float4*)(g_h + (size_t)nb * 256);
    float a1_0 = g_a1[e * 2], a1_1 = g_a1[e * 2 + 1];
    float a2_0 = g_a2[e * 2], a2_1 = g_a2[e * 2 + 1];
    float d0 = g_Dn[nb * 2];     d0 = (d0 > 0.f) ? 1.f / d0 : 0.f;
    float d1 = g_Dn[nb * 2 + 1]; d1 = (d1 > 0.f) ? 1.f / d1 : 0.f;
    float w0 = 0.5f * d0 * a2_0, w1 = 0.5f * d1 * a2_1;
#pragma unroll
    for (int q = 0; q < 2; q++) {
        int f4 = lane + 32 * q;
        float4 va = ha[f4], vb = hb[f4];
        bool hd1 = (f4 >= 32);
        float aa = hd1 ? a1_1 : a1_0;
        float ab = hd1 ? a2_1 : a2_0;
        float w  = hd1 ? w1 : w0;
        float* dst = g_outagg + (size_t)nb * 256 + f4 * 4;
        atomicAdd(dst + 0, w * (aa * va.x + ab * vb.x));
        atomicAdd(dst + 1, w * (aa * va.y + ab * vb.y));
        atomicAdd(dst + 2, w * (aa * va.z + ab * vb.z));
        atomicAdd(dst + 3, w * (aa * va.w + ab * vb.w));
    }
}

// pre-BN output + per-column double sums (one pass)
#define ROWS_PB 100
__global__ void k_prebn(const float* __restrict__ conv_bias, const float* __restrict__ mod_bias,
                        float* __restrict__ dout) {
    int col = threadIdx.x;
    int c = col & 127;
    int r0 = blockIdx.x * ROWS_PB;
    float cb = conv_bias[c];
    float mb = mod_bias[col];
    double s = 0.0, s2 = 0.0;
    for (int i = 0; i < ROWS_PB; i++) {
        size_t off = (size_t)(r0 + i) * 256 + col;
        float v = g_outagg[off] + cb + g_h[off];
        v = (v > 0.f) ? v : expm1f(v);
        v += mb;
        dout[off] = v;
        s += (double)v;
        s2 += (double)v * (double)v;
    }
    atomicAdd(&g_colsum[col], s);
    atomicAdd(&g_colsq[col], s2);
}

__global__ void k_scale(const float* __restrict__ bn_g, const float* __restrict__ bn_b) {
    int c = threadIdx.x;
    double mu = g_colsum[c] / (double)N_ENTC;
    double var = g_colsq[c] / (double)N_ENTC - mu * mu;
    float sc = bn_g[c] * rsqrtf((float)var + 1e-5f);
    g_scale[c] = sc;
    g_shift[c] = bn_b[c] - (float)mu * sc;
}

__global__ void k_norm(float* __restrict__ dout) {
    size_t i = (size_t)blockIdx.x * 256 + threadIdx.x;
    if (i >= (size_t)N_ENTC * 64) return;
    float4 v = ((float4*)dout)[i];
    int col = (int)((i * 4) & 255);
    v.x = v.x * g_scale[col + 0] + g_shift[col + 0];
    v.y = v.y * g_scale[col + 1] + g_shift[col + 1];
    v.z = v.z * g_scale[col + 2] + g_shift[col + 2];
    v.w = v.w * g_scale[col + 3] + g_shift[col + 3];
    ((float4*)dout)[i] = v;
}

// ---------------- launch ----------------
extern "C" void kernel_launch(void* const* d_in, const int* in_sizes, int n_in,
                              void* d_out, int out_size) {
    const float* x        = (const float*)d_in[0];
    const int*   ei       = (const int*)d_in[1];
    // d_in[2] = edge_order (unused)
    const int*   etype    = (const int*)d_in[3];
    const float* rel      = (const float*)d_in[4];
    const int*   ids      = (const int*)d_in[5];
    const float* W_in     = (const float*)d_in[6];
    const float* b_in     = (const float*)d_in[7];
    const float* W_edge   = (const float*)d_in[8];
    const float* b_edge   = (const float*)d_in[9];
    const float* W_sheaf  = (const float*)d_in[10];
    const float* b_sheaf  = (const float*)d_in[11];
    const float* W_conv   = (const float*)d_in[12];
    const float* b_conv   = (const float*)d_in[13];
    const float* conv_bias= (const float*)d_in[14];
    const float* w_rel    = (const float*)d_in[15];
    const float* loop_rel = (const float*)d_in[16];
    const float* mod_bias = (const float*)d_in[17];
    const float* bn_g     = (const float*)d_in[18];
    const float* bn_b     = (const float*)d_in[19];
    float* out = (float*)d_out;

    void* p;
    cudaGetSymbolAddress(&p, g_Dn);     cudaMemsetAsync(p, 0, sizeof(float) * N_ENTC * 2);
    cudaGetSymbolAddress(&p, g_outagg); cudaMemsetAsync(p, 0, sizeof(float) * (size_t)N_ENTC * 256);
    cudaGetSymbolAddress(&p, g_colsum); cudaMemsetAsync(p, 0, sizeof(double) * 256);
    cudaGetSymbolAddress(&p, g_colsq);  cudaMemsetAsync(p, 0, sizeof(double) * 256);

    k_inst<<<N_ROWI, 256>>>(x, ids);
    k_es<<<N_RELC + 1, 256>>>(rel, loop_rel, W_edge, b_edge, W_sheaf);
    k_rout<<<N_RELC, 256>>>(rel, w_rel, out + (size_t)N_ENTC * 256);

    dim3 g1((NTOT + 127) / 128, 2);
    k_gemm1<<<g1, 256>>>(x, W_in, b_in);
    k_gemm2<<<(M2 + 127) / 128, 256>>>(W_conv, b_conv);
    k_xs<<<(NTOT + XS_NODES - 1) / XS_NODES, 64>>>(W_sheaf);

    k_alpha<<<(N_EDGE + 255) / 256, 256>>>(ei, etype, b_sheaf);
    k_agg<<<(N_EDGE * 32 + 255) / 256, 256>>>(ei);

    k_prebn<<<N_ENTC / ROWS_PB, 256>>>(conv_bias, mod_bias, out);
    k_scale<<<1, 256>>>(bn_g, bn_b);
    k_norm<<<(N_ENTC * 64 + 255) / 256, 256>>>(out);
}

// round 16
// speedup vs baseline: 1.1050x; 1.1050x over previous
#include <cuda_runtime.h>
#include <stdint.h>
#include <math.h>

#define N_ENTC 100000
#define N_ROWI 30000
#define NTOT   130000
#define M2     (2 * NTOT)
#define N_EDGE 200000
#define N_RELC 200

// ---------------- scratch (static device globals; no allocation) ----------------
__device__ float g_inst[(size_t)N_ROWI * 256];
__device__ float g_xview[(size_t)NTOT * 256]; // exact fp32 x_all @ W_in + b_in  (FROZEN numerics)
__device__ float g_h[(size_t)NTOT * 256];     // exact fp32 x_view @ W_conv + b_conv
__device__ float g_xs[NTOT * 2];
__device__ float g_a1[N_EDGE * 2];
__device__ float g_a2[N_EDGE * 2];
__device__ float g_Dn[N_ENTC * 2];
__device__ float g_outagg[(size_t)N_ENTC * 256];
__device__ float g_es[(N_RELC + 1) * 2];
__device__ double g_colsum[256];
__device__ double g_colsq[256];
__device__ float g_scale[256];
__device__ float g_shift[256];

// ---------------- direct es, EXACT fp32 ----------------
__global__ void k_es(const float* __restrict__ rel_embed, const float* __restrict__ loop_rel,
                     const float* __restrict__ W_edge, const float* __restrict__ b_edge,
                     const float* __restrict__ W_sheaf) {
    __shared__ float row[256], ev[256];
    int t = threadIdx.x;
    int r = blockIdx.x;
    const float* src = (r < N_RELC) ? rel_embed + (size_t)r * 256 : loop_rel;
    row[t] = src[t];
    __syncthreads();
    float s = 0.f;
    for (int f = 0; f < 256; f++) s = fmaf(row[f], W_edge[(size_t)f * 256 + t], s);
    ev[t] = s + b_edge[t];
    __syncthreads();
    if (t < 2) {
        float acc = 0.f;
        for (int c = 0; c < 128; c++) {
            float em = 0.5f * (ev[c] + ev[c + 128]);
            acc = fmaf(em, W_sheaf[(size_t)(128 + c) * 2 + t], acc);
        }
        g_es[r * 2 + t] = acc;
    }
}

// r_out = rel_embed @ w_rel
__global__ void k_rout(const float* __restrict__ rel_embed, const float* __restrict__ w_rel,
                       float* __restrict__ out) {
    int r = blockIdx.x, c = threadIdx.x;
    __shared__ float row[256];
    row[c] = rel_embed[(size_t)r * 256 + c];
    __syncthreads();
    float s = 0.f;
    for (int f = 0; f < 256; f++) s = fmaf(row[f], w_rel[(size_t)f * 256 + c], s);
    out[(size_t)r * 256 + c] = s;
}

// instance-dict embedding
__global__ void k_inst(const float* __restrict__ x, const int* __restrict__ ids) {
    int r = blockIdx.x, c = threadIdx.x;
    float s = 0.f;
    int cnt = 0;
#pragma unroll
    for (int k = 0; k < 8; k++) {
        int id = ids[r * 8 + k];
        if (id >= 0) { s += x[(size_t)id * 256 + c]; cnt++; }
    }
    g_inst[(size_t)r * 256 + c] = s / (float)cnt;
}

// row/col index mapping for the conflict-free 2x2 quadrant thread tile
__device__ __forceinline__ int quad_idx(int base4, int i) {
    // i in 0..7 -> base4 + i (i<4) or 64 + base4 + (i-4)
    return (i < 4) ? (base4 + i) : (64 + base4 + i - 4);
}

// ---------------- GEMM1 (exact fp32 chains, quadrant tile, double-buffered) ----------------
__global__ void __launch_bounds__(256) k_gemm1(const float* __restrict__ x,
                                               const float* __restrict__ W_in,
                                               const float* __restrict__ b_in) {
    __shared__ float As[2][8][128];
    __shared__ float Bs[2][8][128];
    int tid = threadIdx.x;
    int tx = tid & 15, ty = tid >> 4;
    int rowBase = blockIdx.x * 128;
    int colBase = blockIdx.y * 128;
    float acc[8][8] = {};
    int arow = tid >> 1, acol = (tid & 1) * 4;
    int brow = tid >> 5, bcol = (tid & 31) * 4;
    int gr_a = rowBase + arow;
    bool a_ok = (gr_a < NTOT);
    const float* srcA = a_ok
        ? ((gr_a < N_ENTC) ? x + (size_t)gr_a * 256 : g_inst + (size_t)(gr_a - N_ENTC) * 256)
        : x;

    {
        float4 av = make_float4(0.f, 0.f, 0.f, 0.f);
        if (a_ok) av = *(const float4*)(srcA + acol);
        As[0][acol + 0][arow] = av.x;
        As[0][acol + 1][arow] = av.y;
        As[0][acol + 2][arow] = av.z;
        As[0][acol + 3][arow] = av.w;
        *(float4*)(&Bs[0][brow][bcol]) =
            *(const float4*)(W_in + (size_t)brow * 256 + colBase + bcol);
    }
    __syncthreads();
    int buf = 0;
    for (int k0 = 0; k0 < 256; k0 += 8) {
        float4 av2 = make_float4(0.f, 0.f, 0.f, 0.f), bv2;
        bool nxt = (k0 + 8) < 256;
        if (nxt) {
            if (a_ok) av2 = *(const float4*)(srcA + k0 + 8 + acol);
            bv2 = *(const float4*)(W_in + (size_t)(k0 + 8 + brow) * 256 + colBase + bcol);
        }
#pragma unroll
        for (int kk = 0; kk < 8; kk++) {
            // conflict-free quadrant reads: consecutive float4 per lane
            float4 a0 = *(const float4*)(&As[buf][kk][ty * 4]);
            float4 a1 = *(const float4*)(&As[buf][kk][64 + ty * 4]);
            float4 b0 = *(const float4*)(&Bs[buf][kk][tx * 4]);
            float4 b1 = *(const float4*)(&Bs[buf][kk][64 + tx * 4]);
            float a[8] = {a0.x, a0.y, a0.z, a0.w, a1.x, a1.y, a1.z, a1.w};
            float b[8] = {b0.x, b0.y, b0.z, b0.w, b1.x, b1.y, b1.z, b1.w};
#pragma unroll
            for (int i = 0; i < 8; i++)
#pragma unroll
                for (int j = 0; j < 8; j++) acc[i][j] = fmaf(a[i], b[j], acc[i][j]);
        }
        if (nxt) {
            int nb = buf ^ 1;
            As[nb][acol + 0][arow] = av2.x;
            As[nb][acol + 1][arow] = av2.y;
            As[nb][acol + 2][arow] = av2.z;
            As[nb][acol + 3][arow] = av2.w;
            *(float4*)(&Bs[nb][brow][bcol]) = bv2;
        }
        __syncthreads();
        buf ^= 1;
    }
#pragma unroll
    for (int i = 0; i < 8; i++) {
        int gr = rowBase + quad_idx(ty * 4, i);
        if (gr < NTOT) {
#pragma unroll
            for (int jh = 0; jh < 2; jh++) {
                int col = colBase + (jh ? 64 + tx * 4 : tx * 4);
                int j = jh * 4;
                float4 v;
                v.x = acc[i][j + 0] + b_in[col + 0];
                v.y = acc[i][j + 1] + b_in[col + 1];
                v.z = acc[i][j + 2] + b_in[col + 2];
                v.w = acc[i][j + 3] + b_in[col + 3];
                *(float4*)(g_xview + (size_t)gr * 256 + col) = v;
            }
        }
    }
}

// ---------------- GEMM2 (exact fp32 chains, quadrant tile, double-buffered) ----------------
__global__ void __launch_bounds__(256) k_gemm2(const float* __restrict__ W_conv,
                                               const float* __restrict__ b_conv) {
    __shared__ float As[2][8][128];
    __shared__ float Bs[2][8][128];
    int tid = threadIdx.x;
    int tx = tid & 15, ty = tid >> 4;
    int rowBase = blockIdx.x * 128;
    float acc[8][8] = {};
    int arow = tid >> 1, acol = (tid & 1) * 4;
    int brow = tid >> 5, bcol = (tid & 31) * 4;
    int gr_a = rowBase + arow;
    bool a_ok = (gr_a < M2);
    const float* srcA = g_xview + (size_t)gr_a * 128;

    {
        float4 av = make_float4(0.f, 0.f, 0.f, 0.f);
        if (a_ok) av = *(const float4*)(srcA + acol);
        As[0][acol + 0][arow] = av.x;
        As[0][acol + 1][arow] = av.y;
        As[0][acol + 2][arow] = av.z;
        As[0][acol + 3][arow] = av.w;
        *(float4*)(&Bs[0][brow][bcol]) =
            *(const float4*)(W_conv + (size_t)brow * 128 + bcol);
    }
    __syncthreads();
    int buf = 0;
    for (int k0 = 0; k0 < 128; k0 += 8) {
        float4 av2 = make_float4(0.f, 0.f, 0.f, 0.f), bv2;
        bool nxt = (k0 + 8) < 128;
        if (nxt) {
            if (a_ok) av2 = *(const float4*)(srcA + k0 + 8 + acol);
            bv2 = *(const float4*)(W_conv + (size_t)(k0 + 8 + brow) * 128 + bcol);
        }
#pragma unroll
        for (int kk = 0; kk < 8; kk++) {
            float4 a0 = *(const float4*)(&As[buf][kk][ty * 4]);
            float4 a1 = *(const float4*)(&As[buf][kk][64 + ty * 4]);
            float4 b0 = *(const float4*)(&Bs[buf][kk][tx * 4]);
            float4 b1 = *(const float4*)(&Bs[buf][kk][64 + tx * 4]);
            float a[8] = {a0.x, a0.y, a0.z, a0.w, a1.x, a1.y, a1.z, a1.w};
            float b[8] = {b0.x, b0.y, b0.z, b0.w, b1.x, b1.y, b1.z, b1.w};
#pragma unroll
            for (int i = 0; i < 8; i++)
#pragma unroll
                for (int j = 0; j < 8; j++) acc[i][j] = fmaf(a[i], b[j], acc[i][j]);
        }
        if (nxt) {
            int nb = buf ^ 1;
            As[nb][acol + 0][arow] = av2.x;
            As[nb][acol + 1][arow] = av2.y;
            As[nb][acol + 2][arow] = av2.z;
            As[nb][acol + 3][arow] = av2.w;
            *(float4*)(&Bs[nb][brow][bcol]) = bv2;
        }
        __syncthreads();
        buf ^= 1;
    }
#pragma unroll
    for (int i = 0; i < 8; i++) {
        int gr = rowBase + quad_idx(ty * 4, i);
        if (gr < M2) {
#pragma unroll
            for (int jh = 0; jh < 2; jh++) {
                int col = jh ? 64 + tx * 4 : tx * 4;
                int j = jh * 4;
                float4 v;
                v.x = acc[i][j + 0] + b_conv[col + 0];
                v.y = acc[i][j + 1] + b_conv[col + 1];
                v.z = acc[i][j + 2] + b_conv[col + 2];
                v.w = acc[i][j + 3] + b_conv[col + 3];
                *(float4*)(g_h + (size_t)gr * 128 + col) = v;
            }
        }
    }
}

// ---------------- direct xs, EXACT fp32 chain (FROZEN), smem-staged rows ----------------
#define XS_NODES 32
#define XS_STRIDE 258
__global__ void k_xs(const float* __restrict__ W_sheaf) {
    __shared__ float sx[XS_NODES * XS_STRIDE];
    int t = threadIdx.x;              // 0..63
    int rowBase = blockIdx.x * XS_NODES;
    int nvalid = NTOT - rowBase; if (nvalid > XS_NODES) nvalid = XS_NODES;
    const float2* src = (const float2*)(g_xview + (size_t)rowBase * 256);
    float2* dst = (float2*)sx;
    int total = nvalid * 128;
    for (int i = t; i < total; i += 64) {
        int row = i >> 7, q = i & 127;
        dst[row * 129 + q] = src[i];
    }
    __syncthreads();
    int nl = t >> 1, hd = t & 1;
    if (nl < nvalid) {
        const float* xv = sx + nl * XS_STRIDE;
        float z = 0.f;
        for (int c = 0; c < 128; c++) {
            float m = 0.5f * (xv[c] + xv[c + 128]);
            z = fmaf(m, W_sheaf[c * 2 + hd], z);
        }
        g_xs[(size_t)(rowBase + nl) * 2 + hd] = z;
    }
}

// alpha + Dn (entity slots only)
__global__ void k_alpha(const int* __restrict__ ei, const int* __restrict__ etype,
                        const float* __restrict__ b_sheaf) {
    int e = blockIdx.x * 256 + threadIdx.x;
    if (e >= N_EDGE) return;
    int nb = ei[e];
    int na = ei[N_EDGE + e] + N_ENTC;
    int r = etype[e];
#pragma unroll
    for (int hd = 0; hd < 2; hd++) {
        float base = g_es[r * 2 + hd] + b_sheaf[hd];
        float v1 = tanhf(g_xs[na * 2 + hd] + base);
        float v2 = tanhf(g_xs[nb * 2 + hd] + base);
        g_a1[e * 2 + hd] = v1;
        g_a2[e * 2 + hd] = v2;
        atomicAdd(&g_Dn[nb * 2 + hd], v2 * v2);
    }
}

// main scatter
__global__ void k_agg(const int* __restrict__ ei) {
    int warp = (blockIdx.x * blockDim.x + threadIdx.x) >> 5;
    int lane = threadIdx.x & 31;
    if (warp >= N_EDGE) return;
    int e = warp;
    int nb = ei[e];
    int na = ei[N_EDGE + e] + N_ENTC;
    const float4* ha = (const float4*)(g_h + (size_t)na * 256);
    const float4* hb = (const float4*)(g_h + (size_t)nb * 256);
    float a1_0 = g_a1[e * 2], a1_1 = g_a1[e * 2 + 1];
    float a2_0 = g_a2[e * 2], a2_1 = g_a2[e * 2 + 1];
    float d0 = g_Dn[nb * 2];     d0 = (d0 > 0.f) ? 1.f / d0 : 0.f;
    float d1 = g_Dn[nb * 2 + 1]; d1 = (d1 > 0.f) ? 1.f / d1 : 0.f;
    float w0 = 0.5f * d0 * a2_0, w1 = 0.5f * d1 * a2_1;
#pragma unroll
    for (int q = 0; q < 2; q++) {
        int f4 = lane + 32 * q;
        float4 va = ha[f4], vb = hb[f4];
        bool hd1 = (f4 >= 32);
        float aa = hd1 ? a1_1 : a1_0;
        float ab = hd1 ? a2_1 : a2_0;
        float w  = hd1 ? w1 : w0;
        float* dst = g_outagg + (size_t)nb * 256 + f4 * 4;
        atomicAdd(dst + 0, w * (aa * va.x + ab * vb.x));
        atomicAdd(dst + 1, w * (aa * va.y + ab * vb.y));
        atomicAdd(dst + 2, w * (aa * va.z + ab * vb.z));
        atomicAdd(dst + 3, w * (aa * va.w + ab * vb.w));
    }
}

// pre-BN output + per-column double sums (one pass)
#define ROWS_PB 100
__global__ void k_prebn(const float* __restrict__ conv_bias, const float* __restrict__ mod_bias,
                        float* __restrict__ dout) {
    int col = threadIdx.x;
    int c = col & 127;
    int r0 = blockIdx.x * ROWS_PB;
    float cb = conv_bias[c];
    float mb = mod_bias[col];
    double s = 0.0, s2 = 0.0;
    for (int i = 0; i < ROWS_PB; i++) {
        size_t off = (size_t)(r0 + i) * 256 + col;
        float v = g_outagg[off] + cb + g_h[off];
        v = (v > 0.f) ? v : expm1f(v);
        v += mb;
        dout[off] = v;
        s += (double)v;
        s2 += (double)v * (double)v;
    }
    atomicAdd(&g_colsum[col], s);
    atomicAdd(&g_colsq[col], s2);
}

__global__ void k_scale(const float* __restrict__ bn_g, const float* __restrict__ bn_b) {
    int c = threadIdx.x;
    double mu = g_colsum[c] / (double)N_ENTC;
    double var = g_colsq[c] / (double)N_ENTC - mu * mu;
    float sc = bn_g[c] * rsqrtf((float)var + 1e-5f);
    g_scale[c] = sc;
    g_shift[c] = bn_b[c] - (float)mu * sc;
}

__global__ void k_norm(float* __restrict__ dout) {
    size_t i = (size_t)blockIdx.x * 256 + threadIdx.x;
    if (i >= (size_t)N_ENTC * 64) return;
    float4 v = ((float4*)dout)[i];
    int col = (int)((i * 4) & 255);
    v.x = v.x * g_scale[col + 0] + g_shift[col + 0];
    v.y = v.y * g_scale[col + 1] + g_shift[col + 1];
    v.z = v.z * g_scale[col + 2] + g_shift[col + 2];
    v.w = v.w * g_scale[col + 3] + g_shift[col + 3];
    ((float4*)dout)[i] = v;
}

// ---------------- launch ----------------
extern "C" void kernel_launch(void* const* d_in, const int* in_sizes, int n_in,
                              void* d_out, int out_size) {
    const float* x        = (const float*)d_in[0];
    const int*   ei       = (const int*)d_in[1];
    // d_in[2] = edge_order (unused)
    const int*   etype    = (const int*)d_in[3];
    const float* rel      = (const float*)d_in[4];
    const int*   ids      = (const int*)d_in[5];
    const float* W_in     = (const float*)d_in[6];
    const float* b_in     = (const float*)d_in[7];
    const float* W_edge   = (const float*)d_in[8];
    const float* b_edge   = (const float*)d_in[9];
    const float* W_sheaf  = (const float*)d_in[10];
    const float* b_sheaf  = (const float*)d_in[11];
    const float* W_conv   = (const float*)d_in[12];
    const float* b_conv   = (const float*)d_in[13];
    const float* conv_bias= (const float*)d_in[14];
    const float* w_rel    = (const float*)d_in[15];
    const float* loop_rel = (const float*)d_in[16];
    const float* mod_bias = (const float*)d_in[17];
    const float* bn_g     = (const float*)d_in[18];
    const float* bn_b     = (const float*)d_in[19];
    float* out = (float*)d_out;

    void* p;
    cudaGetSymbolAddress(&p, g_Dn);     cudaMemsetAsync(p, 0, sizeof(float) * N_ENTC * 2);
    cudaGetSymbolAddress(&p, g_outagg); cudaMemsetAsync(p, 0, sizeof(float) * (size_t)N_ENTC * 256);
    cudaGetSymbolAddress(&p, g_colsum); cudaMemsetAsync(p, 0, sizeof(double) * 256);
    cudaGetSymbolAddress(&p, g_colsq);  cudaMemsetAsync(p, 0, sizeof(double) * 256);

    k_inst<<<N_ROWI, 256>>>(x, ids);
    k_es<<<N_RELC + 1, 256>>>(rel, loop_rel, W_edge, b_edge, W_sheaf);
    k_rout<<<N_RELC, 256>>>(rel, w_rel, out + (size_t)N_ENTC * 256);

    dim3 g1((NTOT + 127) / 128, 2);
    k_gemm1<<<g1, 256>>>(x, W_in, b_in);
    k_gemm2<<<(M2 + 127) / 128, 256>>>(W_conv, b_conv);
    k_xs<<<(NTOT + XS_NODES - 1) / XS_NODES, 64>>>(W_sheaf);

    k_alpha<<<(N_EDGE + 255) / 256, 256>>>(ei, etype, b_sheaf);
    k_agg<<<(N_EDGE * 32 + 255) / 256, 256>>>(ei);

    k_prebn<<<N_ENTC / ROWS_PB, 256>>>(conv_bias, mod_bias, out);
    k_scale<<<1, 256>>>(bn_g, bn_b);
    k_norm<<<(N_ENTC * 64 + 255) / 256, 256>>>(out);
}

// round 17
// speedup vs baseline: 1.1973x; 1.0835x over previous
#include <cuda_runtime.h>
#include <stdint.h>
#include <math.h>

#define N_ENTC 100000
#define N_ROWI 30000
#define NTOT   130000
#define M2     (2 * NTOT)
#define N_EDGE 200000
#define N_RELC 200

// ---------------- scratch (static device globals; no allocation) ----------------
__device__ float g_inst[(size_t)N_ROWI * 256];
__device__ float g_xview[(size_t)NTOT * 256]; // exact fp32 x_all @ W_in + b_in  (FROZEN numerics)
__device__ float g_h[(size_t)NTOT * 256];     // exact fp32 x_view @ W_conv + b_conv
__device__ float g_xs[NTOT * 2];
__device__ float g_a1[N_EDGE * 2];
__device__ float g_a2[N_EDGE * 2];
__device__ float g_Dn[N_ENTC * 2];
__device__ float g_outagg[(size_t)N_ENTC * 256];
__device__ float g_es[(N_RELC + 1) * 2];
__device__ double g_colstats[512];            // [0:256) sum, [256:512) sumsq
__device__ float g_scale[256];
__device__ float g_shift[256];

// vectorized global float4 reduction (sm_90+)
__device__ __forceinline__ void red_add_v4(float* dst, float a, float b, float c, float d) {
    asm volatile("red.global.add.v4.f32 [%0], {%1, %2, %3, %4};"
                 :: "l"(dst), "f"(a), "f"(b), "f"(c), "f"(d) : "memory");
}

// ---------------- direct es, EXACT fp32 ----------------
__global__ void k_es(const float* __restrict__ rel_embed, const float* __restrict__ loop_rel,
                     const float* __restrict__ W_edge, const float* __restrict__ b_edge,
                     const float* __restrict__ W_sheaf) {
    __shared__ float row[256], ev[256];
    int t = threadIdx.x;
    int r = blockIdx.x;
    const float* src = (r < N_RELC) ? rel_embed + (size_t)r * 256 : loop_rel;
    row[t] = src[t];
    __syncthreads();
    float s = 0.f;
    for (int f = 0; f < 256; f++) s = fmaf(row[f], W_edge[(size_t)f * 256 + t], s);
    ev[t] = s + b_edge[t];
    __syncthreads();
    if (t < 2) {
        float acc = 0.f;
        for (int c = 0; c < 128; c++) {
            float em = 0.5f * (ev[c] + ev[c + 128]);
            acc = fmaf(em, W_sheaf[(size_t)(128 + c) * 2 + t], acc);
        }
        g_es[r * 2 + t] = acc;
    }
}

// r_out = rel_embed @ w_rel
__global__ void k_rout(const float* __restrict__ rel_embed, const float* __restrict__ w_rel,
                       float* __restrict__ out) {
    int r = blockIdx.x, c = threadIdx.x;
    __shared__ float row[256];
    row[c] = rel_embed[(size_t)r * 256 + c];
    __syncthreads();
    float s = 0.f;
    for (int f = 0; f < 256; f++) s = fmaf(row[f], w_rel[(size_t)f * 256 + c], s);
    out[(size_t)r * 256 + c] = s;
}

// instance-dict embedding: 4 rows per block, float4 per thread (bit-exact per column)
__global__ void k_inst(const float* __restrict__ x, const int* __restrict__ ids) {
    int t = threadIdx.x;
    int r = blockIdx.x * 4 + (t >> 6);        // row
    int c4 = (t & 63) * 4;                    // column group
    float4 s = make_float4(0.f, 0.f, 0.f, 0.f);
    int cnt = 0;
#pragma unroll
    for (int k = 0; k < 8; k++) {
        int id = ids[r * 8 + k];
        if (id >= 0) {
            float4 v = *(const float4*)(x + (size_t)id * 256 + c4);
            s.x += v.x; s.y += v.y; s.z += v.z; s.w += v.w;
            cnt++;
        }
    }
    float inv = 1.f / (float)cnt;
    // match reference: sum / cnt (division, not multiply-by-reciprocal? reference does /)
    s.x = s.x / (float)cnt; s.y = s.y / (float)cnt; s.z = s.z / (float)cnt; s.w = s.w / (float)cnt;
    (void)inv;
    *(float4*)(g_inst + (size_t)r * 256 + c4) = s;
}

// quadrant index helper
__device__ __forceinline__ int quad_idx(int base4, int i) {
    return (i < 4) ? (base4 + i) : (64 + base4 + i - 4);
}

// ---------------- GEMM1 (exact fp32 chains, quadrant tile, double-buffered) ----------------
__global__ void __launch_bounds__(256) k_gemm1(const float* __restrict__ x,
                                               const float* __restrict__ W_in,
                                               const float* __restrict__ b_in) {
    __shared__ float As[2][8][128];
    __shared__ float Bs[2][8][128];
    int tid = threadIdx.x;
    int tx = tid & 15, ty = tid >> 4;
    int rowBase = blockIdx.x * 128;
    int colBase = blockIdx.y * 128;
    float acc[8][8] = {};
    int arow = tid >> 1, acol = (tid & 1) * 4;
    int brow = tid >> 5, bcol = (tid & 31) * 4;
    int gr_a = rowBase + arow;
    bool a_ok = (gr_a < NTOT);
    const float* srcA = a_ok
        ? ((gr_a < N_ENTC) ? x + (size_t)gr_a * 256 : g_inst + (size_t)(gr_a - N_ENTC) * 256)
        : x;

    {
        float4 av = make_float4(0.f, 0.f, 0.f, 0.f);
        if (a_ok) av = *(const float4*)(srcA + acol);
        As[0][acol + 0][arow] = av.x;
        As[0][acol + 1][arow] = av.y;
        As[0][acol + 2][arow] = av.z;
        As[0][acol + 3][arow] = av.w;
        *(float4*)(&Bs[0][brow][bcol]) =
            *(const float4*)(W_in + (size_t)brow * 256 + colBase + bcol);
    }
    __syncthreads();
    int buf = 0;
    for (int k0 = 0; k0 < 256; k0 += 8) {
        float4 av2 = make_float4(0.f, 0.f, 0.f, 0.f), bv2;
        bool nxt = (k0 + 8) < 256;
        if (nxt) {
            if (a_ok) av2 = *(const float4*)(srcA + k0 + 8 + acol);
            bv2 = *(const float4*)(W_in + (size_t)(k0 + 8 + brow) * 256 + colBase + bcol);
        }
#pragma unroll
        for (int kk = 0; kk < 8; kk++) {
            float4 a0 = *(const float4*)(&As[buf][kk][ty * 4]);
            float4 a1 = *(const float4*)(&As[buf][kk][64 + ty * 4]);
            float4 b0 = *(const float4*)(&Bs[buf][kk][tx * 4]);
            float4 b1 = *(const float4*)(&Bs[buf][kk][64 + tx * 4]);
            float a[8] = {a0.x, a0.y, a0.z, a0.w, a1.x, a1.y, a1.z, a1.w};
            float b[8] = {b0.x, b0.y, b0.z, b0.w, b1.x, b1.y, b1.z, b1.w};
#pragma unroll
            for (int i = 0; i < 8; i++)
#pragma unroll
                for (int j = 0; j < 8; j++) acc[i][j] = fmaf(a[i], b[j], acc[i][j]);
        }
        if (nxt) {
            int nb = buf ^ 1;
            As[nb][acol + 0][arow] = av2.x;
            As[nb][acol + 1][arow] = av2.y;
            As[nb][acol + 2][arow] = av2.z;
            As[nb][acol + 3][arow] = av2.w;
            *(float4*)(&Bs[nb][brow][bcol]) = bv2;
        }
        __syncthreads();
        buf ^= 1;
    }
#pragma unroll
    for (int i = 0; i < 8; i++) {
        int gr = rowBase + quad_idx(ty * 4, i);
        if (gr < NTOT) {
#pragma unroll
            for (int jh = 0; jh < 2; jh++) {
                int col = colBase + (jh ? 64 + tx * 4 : tx * 4);
                int j = jh * 4;
                float4 v;
                v.x = acc[i][j + 0] + b_in[col + 0];
                v.y = acc[i][j + 1] + b_in[col + 1];
                v.z = acc[i][j + 2] + b_in[col + 2];
                v.w = acc[i][j + 3] + b_in[col + 3];
                *(float4*)(g_xview + (size_t)gr * 256 + col) = v;
            }
        }
    }
}

// ---------------- GEMM2 (exact fp32 chains, quadrant tile, double-buffered) ----------------
__global__ void __launch_bounds__(256) k_gemm2(const float* __restrict__ W_conv,
                                               const float* __restrict__ b_conv) {
    __shared__ float As[2][8][128];
    __shared__ float Bs[2][8][128];
    int tid = threadIdx.x;
    int tx = tid & 15, ty = tid >> 4;
    int rowBase = blockIdx.x * 128;
    float acc[8][8] = {};
    int arow = tid >> 1, acol = (tid & 1) * 4;
    int brow = tid >> 5, bcol = (tid & 31) * 4;
    int gr_a = rowBase + arow;
    bool a_ok = (gr_a < M2);
    const float* srcA = g_xview + (size_t)gr_a * 128;

    {
        float4 av = make_float4(0.f, 0.f, 0.f, 0.f);
        if (a_ok) av = *(const float4*)(srcA + acol);
        As[0][acol + 0][arow] = av.x;
        As[0][acol + 1][arow] = av.y;
        As[0][acol + 2][arow] = av.z;
        As[0][acol + 3][arow] = av.w;
        *(float4*)(&Bs[0][brow][bcol]) =
            *(const float4*)(W_conv + (size_t)brow * 128 + bcol);
    }
    __syncthreads();
    int buf = 0;
    for (int k0 = 0; k0 < 128; k0 += 8) {
        float4 av2 = make_float4(0.f, 0.f, 0.f, 0.f), bv2;
        bool nxt = (k0 + 8) < 128;
        if (nxt) {
            if (a_ok) av2 = *(const float4*)(srcA + k0 + 8 + acol);
            bv2 = *(const float4*)(W_conv + (size_t)(k0 + 8 + brow) * 128 + bcol);
        }
#pragma unroll
        for (int kk = 0; kk < 8; kk++) {
            float4 a0 = *(const float4*)(&As[buf][kk][ty * 4]);
            float4 a1 = *(const float4*)(&As[buf][kk][64 + ty * 4]);
            float4 b0 = *(const float4*)(&Bs[buf][kk][tx * 4]);
            float4 b1 = *(const float4*)(&Bs[buf][kk][64 + tx * 4]);
            float a[8] = {a0.x, a0.y, a0.z, a0.w, a1.x, a1.y, a1.z, a1.w};
            float b[8] = {b0.x, b0.y, b0.z, b0.w, b1.x, b1.y, b1.z, b1.w};
#pragma unroll
            for (int i = 0; i < 8; i++)
#pragma unroll
                for (int j = 0; j < 8; j++) acc[i][j] = fmaf(a[i], b[j], acc[i][j]);
        }
        if (nxt) {
            int nb = buf ^ 1;
            As[nb][acol + 0][arow] = av2.x;
            As[nb][acol + 1][arow] = av2.y;
            As[nb][acol + 2][arow] = av2.z;
            As[nb][acol + 3][arow] = av2.w;
            *(float4*)(&Bs[nb][brow][bcol]) = bv2;
        }
        __syncthreads();
        buf ^= 1;
    }
#pragma unroll
    for (int i = 0; i < 8; i++) {
        int gr = rowBase + quad_idx(ty * 4, i);
        if (gr < M2) {
#pragma unroll
            for (int jh = 0; jh < 2; jh++) {
                int col = jh ? 64 + tx * 4 : tx * 4;
                int j = jh * 4;
                float4 v;
                v.x = acc[i][j + 0] + b_conv[col + 0];
                v.y = acc[i][j + 1] + b_conv[col + 1];
                v.z = acc[i][j + 2] + b_conv[col + 2];
                v.w = acc[i][j + 3] + b_conv[col + 3];
                *(float4*)(g_h + (size_t)gr * 128 + col) = v;
            }
        }
    }
}

// ---------------- direct xs, EXACT fp32 chain (FROZEN), smem-staged rows ----------------
#define XS_NODES 32
#define XS_STRIDE 258
__global__ void k_xs(const float* __restrict__ W_sheaf) {
    __shared__ float sx[XS_NODES * XS_STRIDE];
    int t = threadIdx.x;              // 0..63
    int rowBase = blockIdx.x * XS_NODES;
    int nvalid = NTOT - rowBase; if (nvalid > XS_NODES) nvalid = XS_NODES;
    const float2* src = (const float2*)(g_xview + (size_t)rowBase * 256);
    float2* dst = (float2*)sx;
    int total = nvalid * 128;
    for (int i = t; i < total; i += 64) {
        int row = i >> 7, q = i & 127;
        dst[row * 129 + q] = src[i];
    }
    __syncthreads();
    int nl = t >> 1, hd = t & 1;
    if (nl < nvalid) {
        const float* xv = sx + nl * XS_STRIDE;
        float z = 0.f;
        for (int c = 0; c < 128; c++) {
            float m = 0.5f * (xv[c] + xv[c + 128]);
            z = fmaf(m, W_sheaf[c * 2 + hd], z);
        }
        g_xs[(size_t)(rowBase + nl) * 2 + hd] = z;
    }
}

// alpha + Dn (entity slots only)
__global__ void k_alpha(const int* __restrict__ ei, const int* __restrict__ etype,
                        const float* __restrict__ b_sheaf) {
    int e = blockIdx.x * 256 + threadIdx.x;
    if (e >= N_EDGE) return;
    int nb = ei[e];
    int na = ei[N_EDGE + e] + N_ENTC;
    int r = etype[e];
#pragma unroll
    for (int hd = 0; hd < 2; hd++) {
        float base = g_es[r * 2 + hd] + b_sheaf[hd];
        float v1 = tanhf(g_xs[na * 2 + hd] + base);
        float v2 = tanhf(g_xs[nb * 2 + hd] + base);
        g_a1[e * 2 + hd] = v1;
        g_a2[e * 2 + hd] = v2;
        atomicAdd(&g_Dn[nb * 2 + hd], v2 * v2);
    }
}

// main scatter: vectorized red.global.add.v4
__global__ void k_agg(const int* __restrict__ ei) {
    int warp = (blockIdx.x * blockDim.x + threadIdx.x) >> 5;
    int lane = threadIdx.x & 31;
    if (warp >= N_EDGE) return;
    int e = warp;
    int nb = ei[e];
    int na = ei[N_EDGE + e] + N_ENTC;
    const float4* ha = (const float4*)(g_h + (size_t)na * 256);
    const float4* hb = (const float4*)(g_h + (size_t)nb * 256);
    float a1_0 = g_a1[e * 2], a1_1 = g_a1[e * 2 + 1];
    float a2_0 = g_a2[e * 2], a2_1 = g_a2[e * 2 + 1];
    float d0 = g_Dn[nb * 2];     d0 = (d0 > 0.f) ? 1.f / d0 : 0.f;
    float d1 = g_Dn[nb * 2 + 1]; d1 = (d1 > 0.f) ? 1.f / d1 : 0.f;
    float w0 = 0.5f * d0 * a2_0, w1 = 0.5f * d1 * a2_1;
#pragma unroll
    for (int q = 0; q < 2; q++) {
        int f4 = lane + 32 * q;
        float4 va = ha[f4], vb = hb[f4];
        bool hd1 = (f4 >= 32);
        float aa = hd1 ? a1_1 : a1_0;
        float ab = hd1 ? a2_1 : a2_0;
        float w  = hd1 ? w1 : w0;
        float* dst = g_outagg + (size_t)nb * 256 + f4 * 4;
        red_add_v4(dst,
                   w * (aa * va.x + ab * vb.x),
                   w * (aa * va.y + ab * vb.y),
                   w * (aa * va.z + ab * vb.z),
                   w * (aa * va.w + ab * vb.w));
    }
}

// pre-BN output + per-column double sums (one pass)
#define ROWS_PB 100
__global__ void k_prebn(const float* __restrict__ conv_bias, const float* __restrict__ mod_bias,
                        float* __restrict__ dout) {
    int col = threadIdx.x;
    int c = col & 127;
    int r0 = blockIdx.x * ROWS_PB;
    float cb = conv_bias[c];
    float mb = mod_bias[col];
    double s = 0.0, s2 = 0.0;
    for (int i = 0; i < ROWS_PB; i++) {
        size_t off = (size_t)(r0 + i) * 256 + col;
        float v = g_outagg[off] + cb + g_h[off];
        v = (v > 0.f) ? v : expm1f(v);
        v += mb;
        dout[off] = v;
        s += (double)v;
        s2 += (double)v * (double)v;
    }
    atomicAdd(&g_colstats[col], s);
    atomicAdd(&g_colstats[256 + col], s2);
}

__global__ void k_scale(const float* __restrict__ bn_g, const float* __restrict__ bn_b) {
    int c = threadIdx.x;
    double mu = g_colstats[c] / (double)N_ENTC;
    double var = g_colstats[256 + c] / (double)N_ENTC - mu * mu;
    float sc = bn_g[c] * rsqrtf((float)var + 1e-5f);
    g_scale[c] = sc;
    g_shift[c] = bn_b[c] - (float)mu * sc;
}

__global__ void k_norm(float* __restrict__ dout) {
    size_t i = (size_t)blockIdx.x * 256 + threadIdx.x;
    if (i >= (size_t)N_ENTC * 64) return;
    float4 v = ((float4*)dout)[i];
    int col = (int)((i * 4) & 255);
    v.x = v.x * g_scale[col + 0] + g_shift[col + 0];
    v.y = v.y * g_scale[col + 1] + g_shift[col + 1];
    v.z = v.z * g_scale[col + 2] + g_shift[col + 2];
    v.w = v.w * g_scale[col + 3] + g_shift[col + 3];
    ((float4*)dout)[i] = v;
}

// ---------------- launch ----------------
extern "C" void kernel_launch(void* const* d_in, const int* in_sizes, int n_in,
                              void* d_out, int out_size) {
    const float* x        = (const float*)d_in[0];
    const int*   ei       = (const int*)d_in[1];
    // d_in[2] = edge_order (unused)
    const int*   etype    = (const int*)d_in[3];
    const float* rel      = (const float*)d_in[4];
    const int*   ids      = (const int*)d_in[5];
    const float* W_in     = (const float*)d_in[6];
    const float* b_in     = (const float*)d_in[7];
    const float* W_edge   = (const float*)d_in[8];
    const float* b_edge   = (const float*)d_in[9];
    const float* W_sheaf  = (const float*)d_in[10];
    const float* b_sheaf  = (const float*)d_in[11];
    const float* W_conv   = (const float*)d_in[12];
    const float* b_conv   = (const float*)d_in[13];
    const float* conv_bias= (const float*)d_in[14];
    const float* w_rel    = (const float*)d_in[15];
    const float* loop_rel = (const float*)d_in[16];
    const float* mod_bias = (const float*)d_in[17];
    const float* bn_g     = (const float*)d_in[18];
    const float* bn_b     = (const float*)d_in[19];
    float* out = (float*)d_out;

    void* p;
    cudaGetSymbolAddress(&p, g_Dn);       cudaMemsetAsync(p, 0, sizeof(float) * N_ENTC * 2);
    cudaGetSymbolAddress(&p, g_outagg);   cudaMemsetAsync(p, 0, sizeof(float) * (size_t)N_ENTC * 256);
    cudaGetSymbolAddress(&p, g_colstats); cudaMemsetAsync(p, 0, sizeof(double) * 512);

    k_inst<<<N_ROWI / 4, 256>>>(x, ids);
    k_es<<<N_RELC + 1, 256>>>(rel, loop_rel, W_edge, b_edge, W_sheaf);
    k_rout<<<N_RELC, 256>>>(rel, w_rel, out + (size_t)N_ENTC * 256);

    dim3 g1((NTOT + 127) / 128, 2);
    k_gemm1<<<g1, 256>>>(x, W_in, b_in);
    k_gemm2<<<(M2 + 127) / 128, 256>>>(W_conv, b_conv);
    k_xs<<<(NTOT + XS_NODES - 1) / XS_NODES, 64>>>(W_sheaf);

    k_alpha<<<(N_EDGE + 255) / 256, 256>>>(ei, etype, b_sheaf);
    k_agg<<<(N_EDGE * 32 + 255) / 256, 256>>>(ei);

    k_prebn<<<N_ENTC / ROWS_PB, 256>>>(conv_bias, mod_bias, out);
    k_scale<<<1, 256>>>(bn_g, bn_b);
    k_norm<<<(N_ENTC * 64 + 255) / 256, 256>>>(out);
}